// round 8
// baseline (speedup 1.0000x reference)
#include <cuda_runtime.h>
#include <cuda_bf16.h>

#define FDIM 224
#define NORD 15
#define NMAX 25008
#define TE   128

__device__ float g_q[NMAX * FDIM];
__device__ float g_k[NMAX * FDIM];
__device__ float g_v[NMAX * FDIM];
__device__ __nv_bfloat16 g_B2[224 * 512];

// smem byte offsets
#define OFF_CUT   0
#define OFF_B2C   512
#define OFF_II    1408
#define OFF_JJ    1920
#define OFF_L0    2432
#define OFF_B1H   4096
#define OFF_B1L   29184
#define OFF_A1H   54272
#define OFF_A1L   68608
#define OFF_QK    4096
#define OFF_PAN   122880
#define PAN_HL    5376
#define PAN_SZ    10752
#define OFF_ALP   122880
#define OFF_YLM   126464
#define SM_TOTAL  144384

__device__ __forceinline__ unsigned smem_u32(const void* p) {
    unsigned a;
    asm("{ .reg .u64 t; cvta.to.shared.u64 t, %1; cvt.u32.u64 %0, t; }" : "=r"(a) : "l"(p));
    return a;
}
__device__ __forceinline__ float silu_f(float x) {
    return __fdividef(x, 1.0f + __expf(-x));
}
__device__ __forceinline__ void ldm4(unsigned* r, unsigned addr) {
    asm volatile("ldmatrix.sync.aligned.m8n8.x4.shared.b16 {%0,%1,%2,%3}, [%4];"
                 : "=r"(r[0]), "=r"(r[1]), "=r"(r[2]), "=r"(r[3]) : "r"(addr) : "memory");
}
__device__ __forceinline__ void mmabf(float* c, const unsigned* a, const unsigned* b) {
    asm volatile("mma.sync.aligned.m16n8k16.row.col.f32.bf16.bf16.f32 "
                 "{%0,%1,%2,%3}, {%4,%5,%6,%7}, {%8,%9}, {%0,%1,%2,%3};"
                 : "+f"(c[0]), "+f"(c[1]), "+f"(c[2]), "+f"(c[3])
                 : "r"(a[0]), "r"(a[1]), "r"(a[2]), "r"(a[3]), "r"(b[0]), "r"(b[1]));
}
__device__ __forceinline__ unsigned packbf(float a, float b) {
    __nv_bfloat162 t = __floats2bfloat162_rn(a, b);
    return *(unsigned*)&t;
}
__device__ __forceinline__ void split2(float a, float b, unsigned& hi, unsigned& lo) {
    __nv_bfloat162 h = __floats2bfloat162_rn(a, b);
    hi = *(unsigned*)&h;
    lo = packbf(a - __bfloat162float(h.x), b - __bfloat162float(h.y));
}

__global__ void zero_kernel(float* out, int n) {
    int i = blockIdx.x * blockDim.x + threadIdx.x;
    if (i < n) out[i] = 0.0f;
}

// g_B2[n][k]: k<256 = bf16_hi(W2cat[c][n]) (c=k&255, 0 for c>=224), k>=256 = lo
__global__ void prep_w2_kernel(const float* __restrict__ W2r, const float* __restrict__ W2s) {
    int i = blockIdx.x * blockDim.x + threadIdx.x;
    if (i >= 224 * 512) return;
    int n = i >> 9, k = i & 511;
    int seg = k >> 8, c = k & 255;
    float v = 0.f;
    if (c < 224) v = (c < 112) ? W2r[c * 224 + n] : W2s[(c - 112) * 224 + n];
    __nv_bfloat16 hv = __float2bfloat16(v);
    g_B2[i] = seg ? __float2bfloat16(v - __bfloat162float(hv)) : hv;
}

__global__ __launch_bounds__(224) void node_kernel(
    const float* __restrict__ x, const float* __restrict__ Wq,
    const float* __restrict__ Wk, const float* __restrict__ Wv, int N)
{
    __shared__ float xs[FDIM];
    const int c = threadIdx.x;
    const int h = c >> 5, i = c & 31;
    const int h2 = c / 56, i2 = c - h2 * 56;
    float4 wq[8], wk[8], wv[14];
    const float4* q4 = (const float4*)(Wq + (h * 32 + i) * 32);
    const float4* k4 = (const float4*)(Wk + (h * 32 + i) * 32);
    const float4* v4 = (const float4*)(Wv + (h2 * 56 + i2) * 56);
#pragma unroll
    for (int m = 0; m < 8; m++) { wq[m] = q4[m]; wk[m] = k4[m]; }
#pragma unroll
    for (int m = 0; m < 14; m++) wv[m] = v4[m];
    for (int n = blockIdx.x; n < N; n += gridDim.x) {
        __syncthreads();
        xs[c] = x[(size_t)n * FDIM + c];
        __syncthreads();
        float aq = 0.f, ak = 0.f, av = 0.f;
        const float4* xb = (const float4*)(xs + h * 32);
#pragma unroll
        for (int m = 0; m < 8; m++) {
            float4 xv = xb[m];
            aq += wq[m].x * xv.x + wq[m].y * xv.y + wq[m].z * xv.z + wq[m].w * xv.w;
            ak += wk[m].x * xv.x + wk[m].y * xv.y + wk[m].z * xv.z + wk[m].w * xv.w;
        }
        const float4* xb2 = (const float4*)(xs + h2 * 56);
#pragma unroll
        for (int m = 0; m < 14; m++) {
            float4 xv = xb2[m];
            av += wv[m].x * xv.x + wv[m].y * xv.y + wv[m].z * xv.z + wv[m].w * xv.w;
        }
        g_q[(size_t)n * FDIM + c] = silu_f(aq);
        g_k[(size_t)n * FDIM + c] = silu_f(ak);
        g_v[(size_t)n * FDIM + c] = av;
    }
}

#define LOAD_PANEL(pp, kss, boff) do {                                        \
    char* _d = smc + OFF_PAN + (boff);                                        \
    for (int _i = t; _i < 448; _i += 256) {                                   \
        int _hl = _i >= 224, _i2 = _i - _hl * 224;                            \
        int _n = _i2 >> 1, _h16 = _i2 & 1;                                    \
        *(uint4*)(_d + _hl * PAN_HL + _n * 48 + _h16 * 16) =                  \
            *(const uint4*)(g_B2 + (size_t)((pp) * 112 + _n) * 512 +          \
                            _hl * 256 + (kss) * 16 + _h16 * 8);               \
    }                                                                         \
} while (0)

__global__ __launch_bounds__(256, 1) void fused_edge_kernel(
    const float* __restrict__ rbf, const float* __restrict__ cut,
    const int* __restrict__ idx_i, const int* __restrict__ idx_j,
    const float* __restrict__ ev,
    const float* __restrict__ W1r, const float* __restrict__ b1r,
    const float* __restrict__ W1s, const float* __restrict__ b1s,
    const float* __restrict__ b2r, const float* __restrict__ b2s,
    const float* __restrict__ ylm,
    float* __restrict__ outx, float* __restrict__ outev, int P)
{
    extern __shared__ char smc[];
    const unsigned sb = smem_u32(smc);
    const int t = threadIdx.x, w = t >> 5, L = t & 31;
    const int e0 = blockIdx.x * TE;
    const int rw = w * 16;

    float* cut_s = (float*)(smc + OFF_CUT);
    float* b2c_s = (float*)(smc + OFF_B2C);
    int*   ii_s  = (int*)(smc + OFF_II);
    int*   jj_s  = (int*)(smc + OFF_JJ);
    float* l0_s  = (float*)(smc + OFF_L0);

    // ---- stage misc + B1 + A1 (hi/lo) ----
    if (t < 224) b2c_s[t] = b2r[t] + b2s[t];
    if (t < TE) {
        int eg = min(e0 + t, P - 1);
        int a = idx_i[eg], b = idx_j[eg];
        ii_s[t] = a; jj_s[t] = b;
        cut_s[t] = (e0 + t < P) ? cut[e0 + t] : 0.f;
        float s0 = 0.f, s1 = 0.f, s2 = 0.f;
        const float* ea = ev + a * NORD;
        const float* eb = ev + b * NORD;
#pragma unroll
        for (int o = 0; o < NORD; o++) {
            float d = eb[o] - ea[o];
            float dd = d * d;
            if (o < 3) s0 += dd; else if (o < 8) s1 += dd; else s2 += dd;
        }
        l0_s[t] = s0; l0_s[128 + t] = s1; l0_s[256 + t] = s2;
    }
    for (int i = t; i < 224 * 48; i += 256) {
        int n = i / 48, k = i - n * 48;
        float v = 0.f;
        if (n < 112) {
            if (k < 32) v = W1r[k * 112 + n];
            else if (k == 35) v = b1r[n];
        } else {
            int n2 = n - 112;
            if (k >= 32 && k < 35) v = W1s[(k - 32) * 112 + n2];
            else if (k == 35) v = b1s[n2];
        }
        __nv_bfloat16 hv = __float2bfloat16(v);
        ((__nv_bfloat16*)(smc + OFF_B1H))[n * 56 + k] = hv;
        ((__nv_bfloat16*)(smc + OFF_B1L))[n * 56 + k] =
            __float2bfloat16(v - __bfloat162float(hv));
    }
    __syncthreads();
    for (int i = t; i < TE * 48; i += 256) {
        int e = i / 48, k = i - e * 48;
        float v = 0.f;
        if (k < 32)      v = ((e0 + e < P) ? rbf[(size_t)(e0 + e) * 32 + k] : 0.f) * cut_s[e];
        else if (k < 35) v = l0_s[(k - 32) * 128 + e];
        else if (k == 35) v = 1.f;
        __nv_bfloat16 hv = __float2bfloat16(v);
        ((__nv_bfloat16*)(smc + OFF_A1H))[e * 56 + k] = hv;
        ((__nv_bfloat16*)(smc + OFF_A1L))[e * 56 + k] =
            __float2bfloat16(v - __bfloat162float(hv));
    }
    __syncthreads();

    // ---- GEMM1: c1[28][4] = A1 @ B1^T ----
    unsigned ah1[3][4], al1[3][4];
#pragma unroll
    for (int ks = 0; ks < 3; ks++) {
        unsigned row = rw + (L & 15), col = ks * 16 + (L >> 4) * 8;
        ldm4(ah1[ks], sb + OFF_A1H + (row * 56 + col) * 2);
        ldm4(al1[ks], sb + OFF_A1L + (row * 56 + col) * 2);
    }
    float c1[28][4];
#pragma unroll
    for (int j = 0; j < 28; j++)
#pragma unroll
        for (int q = 0; q < 4; q++) c1[j][q] = 0.f;
#pragma unroll
    for (int j2 = 0; j2 < 14; j2++) {
        unsigned n0 = j2 * 16 + (L >> 4) * 8 + (L & 7);
#pragma unroll
        for (int ks = 0; ks < 3; ks++) {
            unsigned off = n0 * 112 + ks * 32 + ((L >> 3) & 1) * 16;
            unsigned bh[4], bl[4];
            ldm4(bh, sb + OFF_B1H + off);
            ldm4(bl, sb + OFF_B1L + off);
            mmabf(c1[2 * j2], ah1[ks], bh);
            mmabf(c1[2 * j2], al1[ks], bh);
            mmabf(c1[2 * j2], ah1[ks], bl);
            mmabf(c1[2 * j2 + 1], ah1[ks], bh + 2);
            mmabf(c1[2 * j2 + 1], al1[ks], bh + 2);
            mmabf(c1[2 * j2 + 1], ah1[ks], bl + 2);
        }
    }

    // ---- silu + hi/lo split into GEMM2 A-fragments (in registers) ----
    unsigned a2h[14][4], a2l[14][4];
#pragma unroll
    for (int ks = 0; ks < 14; ks++) {
        float v0 = silu_f(c1[2 * ks][0]), v1 = silu_f(c1[2 * ks][1]);
        float v2 = silu_f(c1[2 * ks][2]), v3 = silu_f(c1[2 * ks][3]);
        float v4 = silu_f(c1[2 * ks + 1][0]), v5 = silu_f(c1[2 * ks + 1][1]);
        float v6 = silu_f(c1[2 * ks + 1][2]), v7 = silu_f(c1[2 * ks + 1][3]);
        split2(v0, v1, a2h[ks][0], a2l[ks][0]);
        split2(v2, v3, a2h[ks][1], a2l[ks][1]);
        split2(v4, v5, a2h[ks][2], a2l[ks][2]);
        split2(v6, v7, a2h[ks][3], a2l[ks][3]);
    }
    __syncthreads();  // B1/A1 reads done; qk region reusable

    // ---- stage qk = q_i * k_j ; preload panel (0,0) ----
    float* qk_s = (float*)(smc + OFF_QK);
    for (int i = t; i < 128 * 56; i += 256) {
        int e = i / 56, c4 = (i - e * 56) * 4;
        float4 q4 = *(const float4*)(g_q + (size_t)ii_s[e] * FDIM + c4);
        float4 k4 = *(const float4*)(g_k + (size_t)jj_s[e] * FDIM + c4);
        float4 r;
        r.x = q4.x * k4.x; r.y = q4.y * k4.y; r.z = q4.z * k4.z; r.w = q4.w * k4.w;
        *(float4*)(qk_s + e * 228 + c4) = r;
    }
    LOAD_PANEL(0, 0, 0);
    __syncthreads();

    // ---- GEMM2: 2 N-passes x 14 k-steps, double-buffered half-panels ----
    const int rA = rw + (L >> 2), rB = rA + 8;
    const float* qA = qk_s + rA * 228;
    const float* qB = qk_s + rB * 228;
    float pA[7], pB[7];
#pragma unroll
    for (int h = 0; h < 7; h++) { pA[h] = 0.f; pB[h] = 0.f; }

#pragma unroll
    for (int p = 0; p < 2; p++) {
        float c2[14][4];
#pragma unroll
        for (int j = 0; j < 14; j++)
#pragma unroll
            for (int q = 0; q < 4; q++) c2[j][q] = 0.f;
#pragma unroll
        for (int ks = 0; ks < 14; ks++) {
            if (ks < 13) { LOAD_PANEL(p, ks + 1, ((ks + 1) & 1) * PAN_SZ); }
            else if (p == 0) { LOAD_PANEL(1, 0, 0); }
            const unsigned pb = sb + OFF_PAN + (ks & 1) * PAN_SZ;
#pragma unroll
            for (int j2 = 0; j2 < 7; j2++) {
                unsigned n0 = j2 * 16 + (L >> 4) * 8 + (L & 7);
                unsigned ba = pb + n0 * 48 + ((L >> 3) & 1) * 16;
                unsigned bh[4], bl[4];
                ldm4(bh, ba);
                ldm4(bl, ba + PAN_HL);
                mmabf(c2[2 * j2], a2h[ks], bh);
                mmabf(c2[2 * j2], a2l[ks], bh);
                mmabf(c2[2 * j2], a2h[ks], bl);
                mmabf(c2[2 * j2 + 1], a2h[ks], bh + 2);
                mmabf(c2[2 * j2 + 1], a2l[ks], bh + 2);
                mmabf(c2[2 * j2 + 1], a2h[ks], bl + 2);
            }
            __syncthreads();
        }
        // accumulate alpha partials for this N-half
#pragma unroll
        for (int j = 0; j < 14; j++) {
            const int jg = p * 14 + j;
            const int h = jg >> 2;
            const int c0 = jg * 8 + 2 * (L & 3);
            float b0 = b2c_s[c0], b1v = b2c_s[c0 + 1];
            pA[h] += qA[c0] * (c2[j][0] + b0) + qA[c0 + 1] * (c2[j][1] + b1v);
            pB[h] += qB[c0] * (c2[j][2] + b0) + qB[c0 + 1] * (c2[j][3] + b1v);
        }
    }

    // ---- reduce + write alpha to smem ----
    float* alp_s = (float*)(smc + OFF_ALP);
#pragma unroll
    for (int h = 0; h < 7; h++) {
        float a = pA[h], b = pB[h];
        a += __shfl_xor_sync(0xffffffffu, a, 1);
        a += __shfl_xor_sync(0xffffffffu, a, 2);
        b += __shfl_xor_sync(0xffffffffu, b, 1);
        b += __shfl_xor_sync(0xffffffffu, b, 2);
        if ((L & 3) == 0) {
            alp_s[h * TE + rA] = a * cut_s[rA];
            alp_s[h * TE + rB] = b * cut_s[rB];
        }
    }
    float* ylm_s = (float*)(smc + OFF_YLM);
    for (int i = t; i < TE * NORD; i += 256)
        ylm_s[i] = (e0 + i / NORD < P) ? ylm[(size_t)e0 * NORD + i] : 0.f;
    __syncthreads();

    // ---- segmented scatter (idx_i sorted; atomics at segment flush) ----
    const int nE = min(TE, P - e0);
    if (t < FDIM) {
        int hc = t / 56;
        const float* arow = alp_s + hc * TE;
        int icur = ii_s[0];
        float a2 = 0.f;
        for (int e = 0; e < nE; e++) {
            int ie = ii_s[e];
            if (ie != icur) {
                atomicAdd(outx + (size_t)icur * FDIM + t, a2);
                a2 = 0.f; icur = ie;
            }
            a2 += arow[e] * g_v[(size_t)jj_s[e] * FDIM + t];
        }
        atomicAdd(outx + (size_t)icur * FDIM + t, a2);
    } else if (t < FDIM + NORD) {
        int o = t - FDIM;
        int hd = (o < 3) ? 4 : (o < 8) ? 5 : 6;
        const float* arow = alp_s + hd * TE;
        int icur = ii_s[0];
        float a2 = 0.f;
        for (int e = 0; e < nE; e++) {
            int ie = ii_s[e];
            if (ie != icur) {
                atomicAdd(outev + (size_t)icur * NORD + o, a2);
                a2 = 0.f; icur = ie;
            }
            a2 += arow[e] * ylm_s[e * NORD + o];
        }
        atomicAdd(outev + (size_t)icur * NORD + o, a2);
    }
}

extern "C" void kernel_launch(void* const* d_in, const int* in_sizes, int n_in,
                              void* d_out, int out_size)
{
    const float* x    = (const float*)d_in[0];
    const float* ev   = (const float*)d_in[1];
    const float* rbf  = (const float*)d_in[2];
    const float* ylm  = (const float*)d_in[3];
    const float* cutp = (const float*)d_in[4];
    const int*   idxi = (const int*)d_in[5];
    const int*   idxj = (const int*)d_in[6];
    const float* W1r  = (const float*)d_in[7];
    const float* b1r  = (const float*)d_in[8];
    const float* W2r  = (const float*)d_in[9];
    const float* b2r  = (const float*)d_in[10];
    const float* W1s  = (const float*)d_in[11];
    const float* b1s  = (const float*)d_in[12];
    const float* W2s  = (const float*)d_in[13];
    const float* b2s  = (const float*)d_in[14];
    const float* Wq   = (const float*)d_in[15];
    const float* Wk   = (const float*)d_in[16];
    const float* Wv   = (const float*)d_in[17];

    int N = in_sizes[0] / FDIM;
    int P = in_sizes[4];
    float* out   = (float*)d_out;
    float* outx  = out;
    float* outev = out + (size_t)N * FDIM;

    zero_kernel<<<(out_size + 255) / 256, 256>>>(out, out_size);
    prep_w2_kernel<<<(224 * 512 + 255) / 256, 256>>>(W2r, W2s);
    node_kernel<<<1024, 224>>>(x, Wq, Wk, Wv, N);

    cudaFuncSetAttribute(fused_edge_kernel,
                         cudaFuncAttributeMaxDynamicSharedMemorySize, SM_TOTAL);
    int nb = (P + TE - 1) / TE;
    fused_edge_kernel<<<nb, 256, SM_TOTAL>>>(rbf, cutp, idxi, idxj, ev,
                                             W1r, b1r, W1s, b1s, b2r, b2s,
                                             ylm, outx, outev, P);
}

// round 10
// speedup vs baseline: 1.5952x; 1.5952x over previous
#include <cuda_runtime.h>
#include <cuda_bf16.h>

#define FDIM 224
#define NORD 15
#define NMAX 25008
#define PMAX 400128
#define TE   128

__device__ float g_q[NMAX * FDIM];
__device__ float g_k[NMAX * FDIM];
__device__ float g_v[NMAX * FDIM];
__device__ float g_alpha[(size_t)PMAX * 8];
__device__ unsigned g_Bf[2 * 14 * 7 * 32 * 8];   // B2 fragments (hi uint4, lo uint4)

// smem byte offsets
#define OFF_CUT   0
#define OFF_B2C   512
#define OFF_II    1408
#define OFF_JJ    1920
#define OFF_L0    2432
#define OFF_B1H   4096
#define OFF_B1L   29184
#define OFF_A1H   54272
#define OFF_A1L   68608
#define OFF_QK    4096
#define SM_TOTAL  120832

__device__ __forceinline__ unsigned smem_u32(const void* p) {
    unsigned a;
    asm("{ .reg .u64 t; cvta.to.shared.u64 t, %1; cvt.u32.u64 %0, t; }" : "=r"(a) : "l"(p));
    return a;
}
__device__ __forceinline__ float silu_f(float x) {
    return __fdividef(x, 1.0f + __expf(-x));
}
__device__ __forceinline__ void ldm4(unsigned* r, unsigned addr) {
    asm volatile("ldmatrix.sync.aligned.m8n8.x4.shared.b16 {%0,%1,%2,%3}, [%4];"
                 : "=r"(r[0]), "=r"(r[1]), "=r"(r[2]), "=r"(r[3]) : "r"(addr) : "memory");
}
__device__ __forceinline__ void mmabf(float* c, const unsigned* a, const unsigned* b) {
    asm volatile("mma.sync.aligned.m16n8k16.row.col.f32.bf16.bf16.f32 "
                 "{%0,%1,%2,%3}, {%4,%5,%6,%7}, {%8,%9}, {%0,%1,%2,%3};"
                 : "+f"(c[0]), "+f"(c[1]), "+f"(c[2]), "+f"(c[3])
                 : "r"(a[0]), "r"(a[1]), "r"(a[2]), "r"(a[3]), "r"(b[0]), "r"(b[1]));
}
__device__ __forceinline__ unsigned packbf(float a, float b) {
    __nv_bfloat162 t = __floats2bfloat162_rn(a, b);
    return *(unsigned*)&t;
}
__device__ __forceinline__ void split2(float a, float b, unsigned& hi, unsigned& lo) {
    __nv_bfloat162 h = __floats2bfloat162_rn(a, b);
    hi = *(unsigned*)&h;
    lo = packbf(a - __bfloat162float(h.x), b - __bfloat162float(h.y));
}

__global__ void zero_kernel(float* out, int n) {
    int i = blockIdx.x * blockDim.x + threadIdx.x;
    if (i < n) out[i] = 0.0f;
}

// Pre-pack W2cat into per-lane MMA B fragments.
// entry id = ((p*14+ks)*7+j2)*32 + L  ->  8 unsigneds: bh[4], bl[4]
__global__ void prep_bf_kernel(const float* __restrict__ W2r, const float* __restrict__ W2s) {
    int id = blockIdx.x * blockDim.x + threadIdx.x;
    if (id >= 6272) return;
    int L = id & 31, rest = id >> 5;
    int j2 = rest % 7, pk = rest / 7;
    int ks = pk % 14, p = pk / 14;
    int n0 = p * 112 + j2 * 16 + (L >> 2);
    int c0 = ks * 16 + (L & 3) * 2;
    unsigned u[8];
#pragma unroll
    for (int i = 0; i < 4; i++) {
        int n = n0 + (i >> 1) * 8;
        int c = c0 + (i & 1) * 8;
        float V0 = (c < 112) ? W2r[c * 224 + n] : W2s[(c - 112) * 224 + n];
        float V1 = (c + 1 < 112) ? W2r[(c + 1) * 224 + n] : W2s[(c + 1 - 112) * 224 + n];
        split2(V0, V1, u[i], u[4 + i]);
    }
    uint4* dst = (uint4*)g_Bf + id * 2;
    dst[0] = make_uint4(u[0], u[1], u[2], u[3]);
    dst[1] = make_uint4(u[4], u[5], u[6], u[7]);
}

__global__ __launch_bounds__(224) void node_kernel(
    const float* __restrict__ x, const float* __restrict__ Wq,
    const float* __restrict__ Wk, const float* __restrict__ Wv, int N)
{
    __shared__ float xs[FDIM];
    const int c = threadIdx.x;
    const int h = c >> 5, i = c & 31;
    const int h2 = c / 56, i2 = c - h2 * 56;
    float4 wq[8], wk[8], wv[14];
    const float4* q4 = (const float4*)(Wq + (h * 32 + i) * 32);
    const float4* k4 = (const float4*)(Wk + (h * 32 + i) * 32);
    const float4* v4 = (const float4*)(Wv + (h2 * 56 + i2) * 56);
#pragma unroll
    for (int m = 0; m < 8; m++) { wq[m] = q4[m]; wk[m] = k4[m]; }
#pragma unroll
    for (int m = 0; m < 14; m++) wv[m] = v4[m];
    for (int n = blockIdx.x; n < N; n += gridDim.x) {
        __syncthreads();
        xs[c] = x[(size_t)n * FDIM + c];
        __syncthreads();
        float aq = 0.f, ak = 0.f, av = 0.f;
        const float4* xb = (const float4*)(xs + h * 32);
#pragma unroll
        for (int m = 0; m < 8; m++) {
            float4 xv = xb[m];
            aq += wq[m].x * xv.x + wq[m].y * xv.y + wq[m].z * xv.z + wq[m].w * xv.w;
            ak += wk[m].x * xv.x + wk[m].y * xv.y + wk[m].z * xv.z + wk[m].w * xv.w;
        }
        const float4* xb2 = (const float4*)(xs + h2 * 56);
#pragma unroll
        for (int m = 0; m < 14; m++) {
            float4 xv = xb2[m];
            av += wv[m].x * xv.x + wv[m].y * xv.y + wv[m].z * xv.z + wv[m].w * xv.w;
        }
        g_q[(size_t)n * FDIM + c] = silu_f(aq);
        g_k[(size_t)n * FDIM + c] = silu_f(ak);
        g_v[(size_t)n * FDIM + c] = av;
    }
}

__global__ __launch_bounds__(256, 1) void fused_edge_kernel(
    const float* __restrict__ rbf, const float* __restrict__ cut,
    const int* __restrict__ idx_i, const int* __restrict__ idx_j,
    const float* __restrict__ ev,
    const float* __restrict__ W1r, const float* __restrict__ b1r,
    const float* __restrict__ W1s, const float* __restrict__ b1s,
    const float* __restrict__ b2r, const float* __restrict__ b2s, int P)
{
    extern __shared__ char smc[];
    const unsigned sb = smem_u32(smc);
    const int t = threadIdx.x, w = t >> 5, L = t & 31;
    const int e0 = blockIdx.x * TE;
    const int rw = w * 16;

    float* cut_s = (float*)(smc + OFF_CUT);
    float* b2c_s = (float*)(smc + OFF_B2C);
    int*   ii_s  = (int*)(smc + OFF_II);
    int*   jj_s  = (int*)(smc + OFF_JJ);
    float* l0_s  = (float*)(smc + OFF_L0);

    // ---- stage misc + B1 + A1 (hi/lo) ----
    if (t < 224) b2c_s[t] = b2r[t] + b2s[t];
    if (t < TE) {
        int eg = min(e0 + t, P - 1);
        int a = idx_i[eg], b = idx_j[eg];
        ii_s[t] = a; jj_s[t] = b;
        cut_s[t] = (e0 + t < P) ? cut[e0 + t] : 0.f;
        float s0 = 0.f, s1 = 0.f, s2 = 0.f;
        const float* ea = ev + a * NORD;
        const float* eb = ev + b * NORD;
#pragma unroll
        for (int o = 0; o < NORD; o++) {
            float d = eb[o] - ea[o];
            float dd = d * d;
            if (o < 3) s0 += dd; else if (o < 8) s1 += dd; else s2 += dd;
        }
        l0_s[t] = s0; l0_s[128 + t] = s1; l0_s[256 + t] = s2;
    }
    for (int i = t; i < 224 * 48; i += 256) {
        int n = i / 48, k = i - n * 48;
        float v = 0.f;
        if (n < 112) {
            if (k < 32) v = W1r[k * 112 + n];
            else if (k == 35) v = b1r[n];
        } else {
            int n2 = n - 112;
            if (k >= 32 && k < 35) v = W1s[(k - 32) * 112 + n2];
            else if (k == 35) v = b1s[n2];
        }
        __nv_bfloat16 hv = __float2bfloat16(v);
        ((__nv_bfloat16*)(smc + OFF_B1H))[n * 56 + k] = hv;
        ((__nv_bfloat16*)(smc + OFF_B1L))[n * 56 + k] =
            __float2bfloat16(v - __bfloat162float(hv));
    }
    __syncthreads();
    for (int i = t; i < TE * 48; i += 256) {
        int e = i / 48, k = i - e * 48;
        float v = 0.f;
        if (k < 32)      v = ((e0 + e < P) ? rbf[(size_t)(e0 + e) * 32 + k] : 0.f) * cut_s[e];
        else if (k < 35) v = l0_s[(k - 32) * 128 + e];
        else if (k == 35) v = 1.f;
        __nv_bfloat16 hv = __float2bfloat16(v);
        ((__nv_bfloat16*)(smc + OFF_A1H))[e * 56 + k] = hv;
        ((__nv_bfloat16*)(smc + OFF_A1L))[e * 56 + k] =
            __float2bfloat16(v - __bfloat162float(hv));
    }
    __syncthreads();

    // ---- GEMM1: c1[28][4] = A1 @ B1^T ----
    unsigned ah1[3][4], al1[3][4];
#pragma unroll
    for (int ks = 0; ks < 3; ks++) {
        unsigned row = rw + (L & 15), col = ks * 16 + (L >> 4) * 8;
        ldm4(ah1[ks], sb + OFF_A1H + (row * 56 + col) * 2);
        ldm4(al1[ks], sb + OFF_A1L + (row * 56 + col) * 2);
    }
    float c1[28][4];
#pragma unroll
    for (int j = 0; j < 28; j++)
#pragma unroll
        for (int q = 0; q < 4; q++) c1[j][q] = 0.f;
#pragma unroll
    for (int j2 = 0; j2 < 14; j2++) {
        unsigned n0 = j2 * 16 + (L >> 4) * 8 + (L & 7);
#pragma unroll
        for (int ks = 0; ks < 3; ks++) {
            unsigned off = n0 * 112 + ks * 32 + ((L >> 3) & 1) * 16;
            unsigned bh[4], bl[4];
            ldm4(bh, sb + OFF_B1H + off);
            ldm4(bl, sb + OFF_B1L + off);
            mmabf(c1[2 * j2], ah1[ks], bh);
            mmabf(c1[2 * j2], al1[ks], bh);
            mmabf(c1[2 * j2], ah1[ks], bl);
            mmabf(c1[2 * j2 + 1], ah1[ks], bh + 2);
            mmabf(c1[2 * j2 + 1], al1[ks], bh + 2);
            mmabf(c1[2 * j2 + 1], ah1[ks], bl + 2);
        }
    }

    // ---- silu + hi/lo split into GEMM2 A-fragments (registers) ----
    unsigned a2h[14][4], a2l[14][4];
#pragma unroll
    for (int ks = 0; ks < 14; ks++) {
        float v0 = silu_f(c1[2 * ks][0]), v1 = silu_f(c1[2 * ks][1]);
        float v2 = silu_f(c1[2 * ks][2]), v3 = silu_f(c1[2 * ks][3]);
        float v4 = silu_f(c1[2 * ks + 1][0]), v5 = silu_f(c1[2 * ks + 1][1]);
        float v6 = silu_f(c1[2 * ks + 1][2]), v7 = silu_f(c1[2 * ks + 1][3]);
        split2(v0, v1, a2h[ks][0], a2l[ks][0]);
        split2(v2, v3, a2h[ks][1], a2l[ks][1]);
        split2(v4, v5, a2h[ks][2], a2l[ks][2]);
        split2(v6, v7, a2h[ks][3], a2l[ks][3]);
    }
    __syncthreads();  // A1/B1 reads done; qk region reusable

    // ---- stage qk = q_i * k_j ----
    float* qk_s = (float*)(smc + OFF_QK);
    for (int i = t; i < 128 * 56; i += 256) {
        int e = i / 56, c4 = (i - e * 56) * 4;
        float4 q4 = *(const float4*)(g_q + (size_t)ii_s[e] * FDIM + c4);
        float4 k4 = *(const float4*)(g_k + (size_t)jj_s[e] * FDIM + c4);
        float4 r;
        r.x = q4.x * k4.x; r.y = q4.y * k4.y; r.z = q4.z * k4.z; r.w = q4.w * k4.w;
        *(float4*)(qk_s + e * 228 + c4) = r;
    }
    __syncthreads();

    // ---- GEMM2: barrier-free; B fragments straight from gmem (L1/L2-resident) ----
    const int rA = rw + (L >> 2), rB = rA + 8;
    const float* qA = qk_s + rA * 228;
    const float* qB = qk_s + rB * 228;
    float pA[7], pB[7];
#pragma unroll
    for (int h = 0; h < 7; h++) { pA[h] = 0.f; pB[h] = 0.f; }
    const uint4* __restrict__ bf = (const uint4*)g_Bf;

#pragma unroll
    for (int p = 0; p < 2; p++) {
        float c2[14][4];
#pragma unroll
        for (int j = 0; j < 14; j++)
#pragma unroll
            for (int q = 0; q < 4; q++) c2[j][q] = 0.f;
#pragma unroll
        for (int ks = 0; ks < 14; ks++) {
            const int base = ((p * 14 + ks) * 7) * 32 + L;
#pragma unroll
            for (int j2 = 0; j2 < 7; j2++) {
                uint4 bh4 = bf[(base + j2 * 32) * 2];
                uint4 bl4 = bf[(base + j2 * 32) * 2 + 1];
                const unsigned* bh = (const unsigned*)&bh4;
                const unsigned* bl = (const unsigned*)&bl4;
                mmabf(c2[2 * j2], a2h[ks], bh);
                mmabf(c2[2 * j2], a2l[ks], bh);
                mmabf(c2[2 * j2], a2h[ks], bl);
                mmabf(c2[2 * j2 + 1], a2h[ks], bh + 2);
                mmabf(c2[2 * j2 + 1], a2l[ks], bh + 2);
                mmabf(c2[2 * j2 + 1], a2h[ks], bl + 2);
            }
        }
#pragma unroll
        for (int j = 0; j < 14; j++) {
            const int jg = p * 14 + j;
            const int h = jg >> 2;
            const int c0 = jg * 8 + 2 * (L & 3);
            float b0 = b2c_s[c0], b1v = b2c_s[c0 + 1];
            pA[h] += qA[c0] * (c2[j][0] + b0) + qA[c0 + 1] * (c2[j][1] + b1v);
            pB[h] += qB[c0] * (c2[j][2] + b0) + qB[c0 + 1] * (c2[j][3] + b1v);
        }
    }

    // ---- reduce + write alpha ----
#pragma unroll
    for (int h = 0; h < 7; h++) {
        float a = pA[h], b = pB[h];
        a += __shfl_xor_sync(0xffffffffu, a, 1);
        a += __shfl_xor_sync(0xffffffffu, a, 2);
        b += __shfl_xor_sync(0xffffffffu, b, 1);
        b += __shfl_xor_sync(0xffffffffu, b, 2);
        if ((L & 3) == 0) {
            int eA = e0 + rA, eB = e0 + rB;
            if (eA < P) g_alpha[(size_t)eA * 8 + h] = a * cut_s[rA];
            if (eB < P) g_alpha[(size_t)eB * 8 + h] = b * cut_s[rB];
        }
    }
}

__global__ __launch_bounds__(256) void scatter_kernel(
    const float* __restrict__ ylm, const int* __restrict__ idx_i,
    const int* __restrict__ idx_j, float* __restrict__ outx,
    float* __restrict__ outev, int P)
{
    __shared__ float alp_s[7 * TE];
    __shared__ float ylm_s[TE * NORD];
    __shared__ int ii_s[TE], jj_s[TE];
    const int t = threadIdx.x;
    const int e0 = blockIdx.x * TE;
    const int nE = min(TE, P - e0);

    if (t < TE) {
        int eg = min(e0 + t, P - 1);
        ii_s[t] = idx_i[eg];
        jj_s[t] = idx_j[eg];
    }
    for (int i = t; i < 7 * TE; i += 256) {
        int h = i >> 7, e = i & 127;
        alp_s[i] = (e0 + e < P) ? g_alpha[(size_t)(e0 + e) * 8 + h] : 0.f;
    }
    for (int i = t; i < TE * NORD; i += 256)
        ylm_s[i] = (e0 + i / NORD < P) ? ylm[(size_t)e0 * NORD + i] : 0.f;
    __syncthreads();

    if (t < FDIM) {
        int hc = t / 56;
        const float* arow = alp_s + hc * TE;
        int icur = ii_s[0];
        float a2 = 0.f;
        for (int e = 0; e < nE; e++) {
            int ie = ii_s[e];
            if (ie != icur) {
                atomicAdd(outx + (size_t)icur * FDIM + t, a2);
                a2 = 0.f; icur = ie;
            }
            a2 += arow[e] * g_v[(size_t)jj_s[e] * FDIM + t];
        }
        atomicAdd(outx + (size_t)icur * FDIM + t, a2);
    } else if (t < FDIM + NORD) {
        int o = t - FDIM;
        int hd = (o < 3) ? 4 : (o < 8) ? 5 : 6;
        const float* arow = alp_s + hd * TE;
        int icur = ii_s[0];
        float a2 = 0.f;
        for (int e = 0; e < nE; e++) {
            int ie = ii_s[e];
            if (ie != icur) {
                atomicAdd(outev + (size_t)icur * NORD + o, a2);
                a2 = 0.f; icur = ie;
            }
            a2 += arow[e] * ylm_s[e * NORD + o];
        }
        atomicAdd(outev + (size_t)icur * NORD + o, a2);
    }
}

extern "C" void kernel_launch(void* const* d_in, const int* in_sizes, int n_in,
                              void* d_out, int out_size)
{
    const float* x    = (const float*)d_in[0];
    const float* ev   = (const float*)d_in[1];
    const float* rbf  = (const float*)d_in[2];
    const float* ylm  = (const float*)d_in[3];
    const float* cutp = (const float*)d_in[4];
    const int*   idxi = (const int*)d_in[5];
    const int*   idxj = (const int*)d_in[6];
    const float* W1r  = (const float*)d_in[7];
    const float* b1r  = (const float*)d_in[8];
    const float* W2r  = (const float*)d_in[9];
    const float* b2r  = (const float*)d_in[10];
    const float* W1s  = (const float*)d_in[11];
    const float* b1s  = (const float*)d_in[12];
    const float* W2s  = (const float*)d_in[13];
    const float* b2s  = (const float*)d_in[14];
    const float* Wq   = (const float*)d_in[15];
    const float* Wk   = (const float*)d_in[16];
    const float* Wv   = (const float*)d_in[17];

    int N = in_sizes[0] / FDIM;
    int P = in_sizes[4];
    float* out   = (float*)d_out;
    float* outx  = out;
    float* outev = out + (size_t)N * FDIM;

    zero_kernel<<<(out_size + 255) / 256, 256>>>(out, out_size);
    prep_bf_kernel<<<(6272 + 255) / 256, 256>>>(W2r, W2s);
    node_kernel<<<1024, 224>>>(x, Wq, Wk, Wv, N);

    cudaFuncSetAttribute(fused_edge_kernel,
                         cudaFuncAttributeMaxDynamicSharedMemorySize, SM_TOTAL);
    int nb = (P + TE - 1) / TE;
    fused_edge_kernel<<<nb, 256, SM_TOTAL>>>(rbf, cutp, idxi, idxj, ev,
                                             W1r, b1r, W1s, b1s, b2r, b2s, P);
    scatter_kernel<<<nb, 256>>>(ylm, idxi, idxj, outx, outev, P);
}